// round 14
// baseline (speedup 1.0000x reference)
#include <cuda_runtime.h>
#include <cstdint>

// ---------------------------------------------------------------------------
// Gazs cell, tf32-direct: ZERO conversion pass.
// mma.m16n8k8.tf32 has the same MAC throughput as fp16 k16 (measured:
// 512 MAC/cyc/SM for both). A and B are cp.async'd as raw fp32 straight
// from h/x/glo and Wi/Wf/Wc (gate-interleave via precomputed pointers).
// cvt.rna applied to A fragments only (kills truncation bias cheaply).
// Tile geometry / stage bytes / epilogue identical to the R13 champion.
// ---------------------------------------------------------------------------

#define BM 128
#define BN_GATE 128
#define BN 384                     // 3 gates * 128 cols (B rows)
#define KC 16                      // fp32 k per stage (64B rows)
#define NSTAGES 4
#define ROW_BYTES 80               // 64B data + 16B pad (20-word stride: conflict-free)
#define A_TILE (BM * ROW_BYTES)            // 10240
#define B_TILE (BN * ROW_BYTES)            // 30720
#define STAGE  (A_TILE + B_TILE)           // 40960
#define DYN_SMEM (NSTAGES * STAGE)         // 163840

#define BATCH 8192
#define HDIM  1024
#define KDIM  4096

// ---- helpers ---------------------------------------------------------------
__device__ __forceinline__ uint32_t smem_u32(const void* p) {
    uint32_t a;
    asm("{ .reg .u64 t; cvta.to.shared.u64 t, %1; cvt.u32.u64 %0, t; }" : "=r"(a) : "l"(p));
    return a;
}
__device__ __forceinline__ void cp16(uint32_t dst, const void* src) {
    asm volatile("cp.async.cg.shared.global [%0], [%1], 16;" :: "r"(dst), "l"(src));
}
__device__ __forceinline__ void cp_commit() {
    asm volatile("cp.async.commit_group;" ::: "memory");
}
__device__ __forceinline__ void wait_groups(int w) {
    if (w == 0)      asm volatile("cp.async.wait_group 0;" ::: "memory");
    else if (w == 1) asm volatile("cp.async.wait_group 1;" ::: "memory");
    else             asm volatile("cp.async.wait_group 2;" ::: "memory");
}
__device__ __forceinline__ void lds32(uint32_t& r, uint32_t addr) {
    asm volatile("ld.shared.b32 %0, [%1];" : "=r"(r) : "r"(addr));
}
__device__ __forceinline__ void cvt_tf32(uint32_t& r) {
    asm volatile("cvt.rna.tf32.f32 %0, %0;" : "+r"(r));
}
__device__ __forceinline__ void mma_tf32(float d[4], const uint32_t a[4],
                                         uint32_t b0, uint32_t b1) {
    asm volatile(
        "mma.sync.aligned.m16n8k8.row.col.f32.tf32.tf32.f32 "
        "{%0,%1,%2,%3},{%4,%5,%6,%7},{%8,%9},{%0,%1,%2,%3};"
        : "+f"(d[0]), "+f"(d[1]), "+f"(d[2]), "+f"(d[3])
        : "r"(a[0]), "r"(a[1]), "r"(a[2]), "r"(a[3]), "r"(b0), "r"(b1));
}
__device__ __forceinline__ float fast_sigmoid(float v) {
    return __fdividef(1.f, 1.f + __expf(-v));
}
__device__ __forceinline__ float fast_tanh(float v) {
    return 1.f - __fdividef(2.f, __expf(2.f * v) + 1.f);
}

// ---- GEMM + fused epilogue, single kernel ------------------------------------
// Per stage (k16): A 128 rows x 64B fp32 + B 384 rows x 64B fp32; 2048 cp16
// (4 per thread: 1 A slot + 3 B slots with precomputed W pointers).
__global__ void __launch_bounds__(512, 1) gazs_gemm_kernel(
    const float* __restrict__ h, const float* __restrict__ x,
    const float* __restrict__ glo,
    const float* __restrict__ Wi, const float* __restrict__ Wf,
    const float* __restrict__ Wc,
    const float* __restrict__ Wib, const float* __restrict__ Wfb,
    const float* __restrict__ Wcb, float* __restrict__ out)
{
    extern __shared__ __align__(128) char smem[];
    const uint32_t sb = smem_u32(smem);

    const int NC   = KDIM / KC;          // 256
    const int tid  = threadIdx.x;
    const int lane = tid & 31;
    const int wid  = tid >> 5;
    const int wn   = wid & 3;            // 4 n-groups, 96 B-rows each
    const int wm   = wid >> 2;           // 4 m-groups, 32 rows each
    const int m0   = blockIdx.y * BM;
    const int n0   = blockIdx.x * BN_GATE;
    const int qr   = lane >> 2;
    const int qc   = lane & 3;

    // ---- per-thread cp.async slots ----------------------------------------
    // slot A: row a_row (0..127), 16B block a_c (0..3)
    const int a_row = tid >> 2;
    const int a_c   = tid & 3;
    const uint32_t a_dst = (uint32_t)a_row * ROW_BYTES + (uint32_t)a_c * 16u;
    // slots B: rows tid/..+512/+1024 of the 384x(4x16B) B tile, gate-interleaved
    const float* wp[3];
    uint32_t bdst[3];
#pragma unroll
    for (int jj = 0; jj < 3; jj++) {
        int t = tid + jj * 512;          // 0..1535
        int row = t >> 2, c = t & 3;     // row 0..383
        int b = row / 24, rem = row % 24;
        int g = rem >> 3, w = rem & 7;
        int n = n0 + b * 8 + w;
        const float* W = (g == 0) ? Wi : (g == 1) ? Wf : Wc;
        wp[jj] = W + (size_t)n * KDIM + c * 4;
        bdst[jj] = (uint32_t)A_TILE + (uint32_t)row * ROW_BYTES + (uint32_t)c * 16u;
    }

    // ---- fragment base addresses (conflict-free: 20-word row stride) ------
    const uint32_t a_fb = (uint32_t)((wm * 32 + qr) * ROW_BYTES + qc * 4);
    const uint32_t b_fb = (uint32_t)(A_TILE + (wn * 96 + qr) * ROW_BYTES + qc * 4);

    float acc[2][12][4];
#pragma unroll
    for (int mt = 0; mt < 2; mt++)
#pragma unroll
        for (int nt = 0; nt < 12; nt++)
#pragma unroll
            for (int c = 0; c < 4; c++) acc[mt][nt][c] = 0.f;

    // ---- stage issue (4 cp16 per thread) -----------------------------------
    auto issue = [&](uint32_t sbase, int kc) {
        const int k0 = kc * KC;
        const float* ab; int astr, ac;
        if (k0 < HDIM)          { ab = h;   astr = HDIM;     ac = k0; }
        else if (k0 < 3 * HDIM) { ab = x;   astr = 2 * HDIM; ac = k0 - HDIM; }
        else                    { ab = glo; astr = HDIM;     ac = k0 - 3 * HDIM; }
        cp16(sbase + a_dst, ab + (size_t)(m0 + a_row) * astr + ac + a_c * 4);
#pragma unroll
        for (int jj = 0; jj < 3; jj++)
            cp16(sbase + bdst[jj], wp[jj] + k0);
        cp_commit();
    };

    // prologue: 3 stages in flight
#pragma unroll
    for (int s = 0; s < NSTAGES - 1; s++)
        issue(sb + (uint32_t)s * STAGE, s);

    for (int kc = 0; kc < NC; kc++) {
        int w = NC - 1 - kc; if (w > NSTAGES - 2) w = NSTAGES - 2;
        wait_groups(w);
        __syncthreads();

        int pf = kc + NSTAGES - 1;
        if (pf < NC)
            issue(sb + (uint32_t)(pf & 3) * STAGE, pf);

        const uint32_t St = sb + (uint32_t)(kc & 3) * STAGE;

#pragma unroll
        for (int s = 0; s < 2; s++) {            // two k8 steps
            uint32_t a[2][4];
#pragma unroll
            for (int mt = 0; mt < 2; mt++) {
                uint32_t base = St + a_fb + (uint32_t)(mt * 16 * ROW_BYTES) + (uint32_t)s * 32;
                lds32(a[mt][0], base);
                lds32(a[mt][1], base + 8 * ROW_BYTES);
                lds32(a[mt][2], base + 16);
                lds32(a[mt][3], base + 8 * ROW_BYTES + 16);
                cvt_tf32(a[mt][0]); cvt_tf32(a[mt][1]);
                cvt_tf32(a[mt][2]); cvt_tf32(a[mt][3]);
            }
            const uint32_t bb = St + b_fb + (uint32_t)s * 32;
            uint32_t bc0, bc1, bn0, bn1;
            lds32(bc0, bb);
            lds32(bc1, bb + 16);
#pragma unroll
            for (int nt = 0; nt < 12; nt++) {
                if (nt < 11) {
                    lds32(bn0, bb + (uint32_t)((nt + 1) * 8 * ROW_BYTES));
                    lds32(bn1, bb + (uint32_t)((nt + 1) * 8 * ROW_BYTES) + 16);
                }
                mma_tf32(acc[0][nt], a[0], bc0, bc1);
                mma_tf32(acc[1][nt], a[1], bc0, bc1);
                bc0 = bn0; bc1 = bn1;
            }
        }
    }

    // ---- epilogue: in-register gate blend (identical to champion) ----------
#pragma unroll
    for (int mt = 0; mt < 2; mt++) {
        const int rb = m0 + wm * 32 + mt * 16 + qr;
#pragma unroll
        for (int bl = 0; bl < 4; bl++) {
            const int n = n0 + (wn * 4 + bl) * 8 + qc * 2;
            const float bi0 = __ldg(Wib + n), bi1 = __ldg(Wib + n + 1);
            const float bf0 = __ldg(Wfb + n), bf1 = __ldg(Wfb + n + 1);
            const float bc0 = __ldg(Wcb + n), bc1 = __ldg(Wcb + n + 1);
            const float* ai = acc[mt][bl * 3 + 0];
            const float* af = acc[mt][bl * 3 + 1];
            const float* ac = acc[mt][bl * 3 + 2];
#pragma unroll
            for (int rs = 0; rs < 2; rs++) {
                const int row = rb + rs * 8;
                const int i0 = rs * 2;
                float2 hv = *(const float2*)(h + (size_t)row * HDIM + n);

                float ig0 = fast_sigmoid(ai[i0] + bi0);
                float ig1 = fast_sigmoid(ai[i0 + 1] + bi1);
                float fg0 = fast_sigmoid(af[i0] + bf0);
                float fg1 = fast_sigmoid(af[i0 + 1] + bf1);
                float cg0 = fast_tanh(ac[i0] + bc0);
                float cg1 = fast_tanh(ac[i0 + 1] + bc1);
                float al0 = fast_sigmoid(ig0 - fg0);
                float al1 = fast_sigmoid(ig1 - fg1);

                float2 ov;
                ov.x = fmaf(al0, cg0 - hv.x, hv.x);
                ov.y = fmaf(al1, cg1 - hv.y, hv.y);
                *(float2*)(out + (size_t)row * HDIM + n) = ov;
            }
        }
    }
}

extern "C" void kernel_launch(void* const* d_in, const int* in_sizes, int n_in,
                              void* d_out, int out_size)
{
    const float* h   = (const float*)d_in[0];
    const float* x   = (const float*)d_in[1];
    const float* glo = (const float*)d_in[2];
    const float* Wi  = (const float*)d_in[3];
    const float* Wib = (const float*)d_in[4];
    const float* Wf  = (const float*)d_in[5];
    const float* Wfb = (const float*)d_in[6];
    const float* Wc  = (const float*)d_in[7];
    const float* Wcb = (const float*)d_in[8];
    float* out = (float*)d_out;

    cudaFuncSetAttribute(gazs_gemm_kernel,
                         cudaFuncAttributeMaxDynamicSharedMemorySize, DYN_SMEM);

    dim3 grid(HDIM / BN_GATE, BATCH / BM);   // (8, 64) = 512 CTAs, single kernel
    gazs_gemm_kernel<<<grid, 512, DYN_SMEM>>>(h, x, glo, Wi, Wf, Wc,
                                              Wib, Wfb, Wcb, out);
}

// round 15
// speedup vs baseline: 2.1717x; 2.1717x over previous
#include <cuda_runtime.h>
#include <cuda_fp16.h>
#include <cstdint>

// ---------------------------------------------------------------------------
// Gazs cell, legacy tensor-core path, fp16 in / fp32 accum. FINAL (== R13).
//   GEMM: 164KB smem, 512 thr, CTA 128x384, warp m32xn96 — measured at the
//         mma.sync MAC floor (512 MAC/cyc/SM; every variation regressed).
//   Conv: grid-stride, __ldcs streaming reads, 16B stores (near roofline).
// Survey that led here: tf32 k8 = rt8/1024MAC, fp16 k16 = rt16/2048MAC
// (same MAC rate, fp16 wins on operand-path issue cost); f16-acc = same rate;
// s8 IMMA ~490 cyc (microcoded); scalar-LDS operands explode issue pressure;
// >164KB smem costs the GEMM 11-18us; h-prefetch never pays.
// ---------------------------------------------------------------------------

#define BM 128
#define BN_GATE 128
#define BN 384                     // 3 gates * 128 cols (B rows)
#define KC 32                      // fp16 k per stage (64B rows)
#define NSTAGES 4
#define ROW_BYTES 80               // 64B data + 16B pad
#define A_TILE (BM * ROW_BYTES)            // 10240
#define B_TILE (BN * ROW_BYTES)            // 30720
#define STAGE  (A_TILE + B_TILE)           // 40960
#define DYN_SMEM (NSTAGES * STAGE)         // 163840

#define BATCH 8192
#define HDIM  1024
#define KDIM  4096
#define TOT_ROWS (BATCH + 3 * HDIM)        // 11264

__device__ __align__(16) __half A16[(size_t)BATCH * KDIM];
__device__ __align__(16) __half W16[(size_t)3 * HDIM * KDIM];

// ---- helpers ---------------------------------------------------------------
__device__ __forceinline__ uint32_t smem_u32(const void* p) {
    uint32_t a;
    asm("{ .reg .u64 t; cvta.to.shared.u64 t, %1; cvt.u32.u64 %0, t; }" : "=r"(a) : "l"(p));
    return a;
}
__device__ __forceinline__ void cp16(uint32_t dst, const void* src) {
    asm volatile("cp.async.cg.shared.global [%0], [%1], 16;" :: "r"(dst), "l"(src));
}
__device__ __forceinline__ void cp_commit() {
    asm volatile("cp.async.commit_group;" ::: "memory");
}
__device__ __forceinline__ void wait_groups(int w) {
    if (w == 0)      asm volatile("cp.async.wait_group 0;" ::: "memory");
    else if (w == 1) asm volatile("cp.async.wait_group 1;" ::: "memory");
    else             asm volatile("cp.async.wait_group 2;" ::: "memory");
}
__device__ __forceinline__ void ldm_x4(uint32_t r[4], uint32_t addr) {
    asm volatile("ldmatrix.sync.aligned.m8n8.x4.shared.b16 {%0,%1,%2,%3}, [%4];"
        : "=r"(r[0]), "=r"(r[1]), "=r"(r[2]), "=r"(r[3]) : "r"(addr));
}
__device__ __forceinline__ void mma_f16(float d[4], const uint32_t a[4],
                                        uint32_t b0, uint32_t b1) {
    asm volatile(
        "mma.sync.aligned.m16n8k16.row.col.f32.f16.f16.f32 "
        "{%0,%1,%2,%3},{%4,%5,%6,%7},{%8,%9},{%0,%1,%2,%3};"
        : "+f"(d[0]), "+f"(d[1]), "+f"(d[2]), "+f"(d[3])
        : "r"(a[0]), "r"(a[1]), "r"(a[2]), "r"(a[3]), "r"(b0), "r"(b1));
}
__device__ __forceinline__ float fast_sigmoid(float v) {
    return __fdividef(1.f, 1.f + __expf(-v));
}
__device__ __forceinline__ float fast_tanh(float v) {
    return 1.f - __fdividef(2.f, __expf(2.f * v) + 1.f);
}
__device__ __forceinline__ float4 ldcs4(const float* p) {
    float4 v;
    asm volatile("ld.global.cs.v4.f32 {%0,%1,%2,%3}, [%4];"
        : "=f"(v.x), "=f"(v.y), "=f"(v.z), "=f"(v.w) : "l"(p));
    return v;
}
__device__ __forceinline__ void cvt_store8(__half* dst, float4 a, float4 b) {
    __half2 p0 = __floats2half2_rn(a.x, a.y);
    __half2 p1 = __floats2half2_rn(a.z, a.w);
    __half2 p2 = __floats2half2_rn(b.x, b.y);
    __half2 p3 = __floats2half2_rn(b.z, b.w);
    uint4 u;
    u.x = *(const uint32_t*)&p0;
    u.y = *(const uint32_t*)&p1;
    u.z = *(const uint32_t*)&p2;
    u.w = *(const uint32_t*)&p3;
    *(uint4*)dst = u;
}

// ---- phase 1: converter, grid-stride over 11264 rows, 16B stores -------------
// rows [0, 8192): A = [h|x|glo]; rows [8192, 11264): W, gate-interleaved:
// W16 row j, j = b*24 + g*8 + w  (b = n8 block, g = gate, w = col in block)
__global__ void conv_kernel(const float* __restrict__ h, const float* __restrict__ x,
                            const float* __restrict__ glo,
                            const float* __restrict__ Wi, const float* __restrict__ Wf,
                            const float* __restrict__ Wc)
{
#pragma unroll 1
    for (int row = blockIdx.x; row < TOT_ROWS; row += gridDim.x) {
        if (row < BATCH) {
            const int m = row;
            __half* dst = A16 + (size_t)m * KDIM;
            const float* h_r = h + (size_t)m * HDIM;
            const float* x_r = x + (size_t)m * 2 * HDIM;
            const float* g_r = glo + (size_t)m * HDIM;
#pragma unroll
            for (int i = 0; i < 2; i++) {
                int k = (threadIdx.x + i * 256) * 8;
                const float* src = (k < HDIM) ? (h_r + k)
                                 : (k < 3 * HDIM) ? (x_r + (k - HDIM))
                                 : (g_r + (k - 3 * HDIM));
                float4 v0 = ldcs4(src);
                float4 v1 = ldcs4(src + 4);
                cvt_store8(dst + k, v0, v1);
            }
        } else {
            const int j = row - BATCH;
            const int b = j / 24, rem = j % 24;
            const int g = rem >> 3, w = rem & 7;
            const int n = b * 8 + w;
            const float* src_r = ((g == 0) ? Wi : (g == 1) ? Wf : Wc) + (size_t)n * KDIM;
            __half* dst = W16 + (size_t)j * KDIM;
#pragma unroll
            for (int i = 0; i < 2; i++) {
                int k = (threadIdx.x + i * 256) * 8;
                float4 v0 = ldcs4(src_r + k);
                float4 v1 = ldcs4(src_r + k + 4);
                cvt_store8(dst + k, v0, v1);
            }
        }
    }
}

// ---- phase 2: GEMM + fused epilogue -------------------------------------------
// Per stage: A 128 rows x 64B + B 384 rows x 64B, stride 80B; 2048 cp16.
__device__ __forceinline__ void issue_stage(uint32_t sbase, int tid, int kc, int m0, int rbase)
{
    const int k0 = kc * KC;
#pragma unroll
    for (int jj = 0; jj < 4; jj++) {
        int idx = tid + (jj << 9);
        if (idx < 512) {                        // A tile: 128 rows * 4
            int row = idx >> 2, c = idx & 3;
            const __half* src = A16 + (size_t)(m0 + row) * KDIM + k0 + c * 8;
            cp16(sbase + (uint32_t)row * ROW_BYTES + (uint32_t)c * 16u, src);
        } else {                                // B tile: 384 rows * 4
            int t = idx - 512;
            int row = t >> 2, c = t & 3;
            const __half* src = W16 + (size_t)(rbase + row) * KDIM + k0 + c * 8;
            cp16(sbase + A_TILE + (uint32_t)row * ROW_BYTES + (uint32_t)c * 16u, src);
        }
    }
    cp_commit();
}

__global__ void __launch_bounds__(512, 1) gazs_gemm_kernel(
    const float* __restrict__ h,
    const float* __restrict__ Wib, const float* __restrict__ Wfb,
    const float* __restrict__ Wcb, float* __restrict__ out)
{
    extern __shared__ __align__(128) char smem[];
    const uint32_t sb = smem_u32(smem);

    const int NC   = KDIM / KC;          // 128
    const int tid  = threadIdx.x;
    const int lane = tid & 31;
    const int wid  = tid >> 5;
    const int wn   = wid & 3;            // 4 n-groups, 96 B-rows each
    const int wm   = wid >> 2;           // 4 m-groups, 32 rows each
    const int m0   = blockIdx.y * BM;
    const int n0   = blockIdx.x * BN_GATE;
    const int rbase = blockIdx.x * BN;   // W16 row base
    const int qr   = lane >> 2;
    const int qc   = lane & 3;

    const uint32_t a_lb = (uint32_t)((wm * 32 + (lane & 15)) * ROW_BYTES + (lane >> 4) * 16);
    const uint32_t b_lb = (uint32_t)((wn * 96 + (lane & 7) + ((lane & 16) ? 8 : 0)) * ROW_BYTES
                                     + ((lane >> 3) & 1) * 16);

    float acc[2][12][4];
#pragma unroll
    for (int mt = 0; mt < 2; mt++)
#pragma unroll
        for (int nt = 0; nt < 12; nt++)
#pragma unroll
            for (int c = 0; c < 4; c++) acc[mt][nt][c] = 0.f;

    // prologue: 3 stages in flight
#pragma unroll
    for (int s = 0; s < NSTAGES - 1; s++)
        issue_stage(sb + (uint32_t)s * STAGE, tid, s, m0, rbase);

    for (int kc = 0; kc < NC; kc++) {
        int w = NC - 1 - kc; if (w > NSTAGES - 2) w = NSTAGES - 2;
        wait_groups(w);
        __syncthreads();

        int pf = kc + NSTAGES - 1;
        if (pf < NC)
            issue_stage(sb + (uint32_t)(pf & 3) * STAGE, tid, pf, m0, rbase);

        const uint32_t As = sb + (uint32_t)(kc & 3) * STAGE;
        const uint32_t Bs = As + A_TILE;

#pragma unroll
        for (int s = 0; s < 2; s++) {
            uint32_t a0[4], a1[4];
            ldm_x4(a0, As + a_lb + (uint32_t)s * 32);
            ldm_x4(a1, As + a_lb + (uint32_t)(16 * ROW_BYTES) + (uint32_t)s * 32);

            uint32_t bcur[4], bnxt[4];
            ldm_x4(bcur, Bs + b_lb + (uint32_t)s * 32);
#pragma unroll
            for (int nb = 0; nb < 6; nb++) {
                if (nb < 5)
                    ldm_x4(bnxt, Bs + b_lb + (uint32_t)((nb + 1) * 16 * ROW_BYTES)
                                 + (uint32_t)s * 32);
                mma_f16(acc[0][2 * nb],     a0, bcur[0], bcur[1]);
                mma_f16(acc[0][2 * nb + 1], a0, bcur[2], bcur[3]);
                mma_f16(acc[1][2 * nb],     a1, bcur[0], bcur[1]);
                mma_f16(acc[1][2 * nb + 1], a1, bcur[2], bcur[3]);
#pragma unroll
                for (int q = 0; q < 4; q++) bcur[q] = bnxt[q];
            }
        }
    }

    // ---- epilogue: in-register gate blend --------------------------------
#pragma unroll
    for (int mt = 0; mt < 2; mt++) {
        const int rb = m0 + wm * 32 + mt * 16 + qr;
#pragma unroll
        for (int bl = 0; bl < 4; bl++) {
            const int n = n0 + (wn * 4 + bl) * 8 + qc * 2;
            const float bi0 = __ldg(Wib + n), bi1 = __ldg(Wib + n + 1);
            const float bf0 = __ldg(Wfb + n), bf1 = __ldg(Wfb + n + 1);
            const float bc0 = __ldg(Wcb + n), bc1 = __ldg(Wcb + n + 1);
            const float* ai = acc[mt][bl * 3 + 0];
            const float* af = acc[mt][bl * 3 + 1];
            const float* ac = acc[mt][bl * 3 + 2];
#pragma unroll
            for (int rs = 0; rs < 2; rs++) {
                const int row = rb + rs * 8;
                const int i0 = rs * 2;
                float2 hv = *(const float2*)(h + (size_t)row * HDIM + n);

                float ig0 = fast_sigmoid(ai[i0] + bi0);
                float ig1 = fast_sigmoid(ai[i0 + 1] + bi1);
                float fg0 = fast_sigmoid(af[i0] + bf0);
                float fg1 = fast_sigmoid(af[i0 + 1] + bf1);
                float cg0 = fast_tanh(ac[i0] + bc0);
                float cg1 = fast_tanh(ac[i0 + 1] + bc1);
                float al0 = fast_sigmoid(ig0 - fg0);
                float al1 = fast_sigmoid(ig1 - fg1);

                float2 ov;
                ov.x = fmaf(al0, cg0 - hv.x, hv.x);
                ov.y = fmaf(al1, cg1 - hv.y, hv.y);
                *(float2*)(out + (size_t)row * HDIM + n) = ov;
            }
        }
    }
}

extern "C" void kernel_launch(void* const* d_in, const int* in_sizes, int n_in,
                              void* d_out, int out_size)
{
    const float* h   = (const float*)d_in[0];
    const float* x   = (const float*)d_in[1];
    const float* glo = (const float*)d_in[2];
    const float* Wi  = (const float*)d_in[3];
    const float* Wib = (const float*)d_in[4];
    const float* Wf  = (const float*)d_in[5];
    const float* Wfb = (const float*)d_in[6];
    const float* Wc  = (const float*)d_in[7];
    const float* Wcb = (const float*)d_in[8];
    float* out = (float*)d_out;

    cudaFuncSetAttribute(gazs_gemm_kernel,
                         cudaFuncAttributeMaxDynamicSharedMemorySize, DYN_SMEM);

    conv_kernel<<<1184, 256>>>(h, x, glo, Wi, Wf, Wc);   // grid-stride, 8 CTAs/SM

    dim3 grid(HDIM / BN_GATE, BATCH / BM);   // (8, 64) = 512 CTAs
    gazs_gemm_kernel<<<grid, 512, DYN_SMEM>>>(h, Wib, Wfb, Wcb, out);
}